// round 7
// baseline (speedup 1.0000x reference)
#include <cuda_runtime.h>
#include <cstdint>

#define BB 32
#define SS 2048
#define DDIM 64
#define TQ 64
#define TK 64
#define NKT 32
#define NTH 256

// bf16 tile row stride: 72 elems = 144 bytes (16B-aligned, ldmatrix conflict-free)
#define RS 144
// smem byte offsets
#define OQHI 0u
#define OQLO 9216u
#define OKHI 18432u
#define OKLO 27648u
#define OVHI 36864u
#define OVLO 46080u
#define ORAWK 55296u          // raw f32 K stage (16 KB)
#define ORAWV 71680u          // raw f32 V stage (16 KB)
#define SMEMSZ 88064u
// epilogue reduce area reuses the Q region [0, 18432)
#define ORED  0u        // fp32 [64][68] O partials
#define OLBUF 17408u    // fp32 [128] row-sum partials
#define OLINV 17920u    // fp32 [64] inverse row sums

// ---------------- helpers ----------------
__device__ __forceinline__ uint32_t s2u(const void* p) {
    uint32_t a;
    asm("{ .reg .u64 t; cvta.to.shared.u64 t, %1; cvt.u32.u64 %0, t; }" : "=r"(a) : "l"(p));
    return a;
}
__device__ __forceinline__ void split2(float a, float b, uint32_t& hi, uint32_t& lo) {
    uint32_t h;
    asm("cvt.rn.bf16x2.f32 %0, %1, %2;" : "=r"(h) : "f"(b), "f"(a));
    float fa = __uint_as_float(h << 16);
    float fb = __uint_as_float(h & 0xFFFF0000u);
    float la = a - fa, lb = b - fb;
    asm("cvt.rn.bf16x2.f32 %0, %1, %2;" : "=r"(lo) : "f"(lb), "f"(la));
    hi = h;
}
__device__ __forceinline__ uint32_t packbf(float lo_e, float hi_e) {
    uint32_t r;
    asm("cvt.rn.bf16x2.f32 %0, %1, %2;" : "=r"(r) : "f"(hi_e), "f"(lo_e));
    return r;
}
__device__ __forceinline__ void ldm4(uint32_t& r0, uint32_t& r1, uint32_t& r2, uint32_t& r3, uint32_t a) {
    asm volatile("ldmatrix.sync.aligned.m8n8.x4.shared.b16 {%0,%1,%2,%3}, [%4];"
                 : "=r"(r0), "=r"(r1), "=r"(r2), "=r"(r3) : "r"(a));
}
__device__ __forceinline__ void ldm4t(uint32_t& r0, uint32_t& r1, uint32_t& r2, uint32_t& r3, uint32_t a) {
    asm volatile("ldmatrix.sync.aligned.m8n8.x4.trans.shared.b16 {%0,%1,%2,%3}, [%4];"
                 : "=r"(r0), "=r"(r1), "=r"(r2), "=r"(r3) : "r"(a));
}
__device__ __forceinline__ void mma16816(float* c, const uint32_t* a, uint32_t b0, uint32_t b1) {
    asm volatile(
        "mma.sync.aligned.m16n8k16.row.col.f32.bf16.bf16.f32 "
        "{%0,%1,%2,%3}, {%4,%5,%6,%7}, {%8,%9}, {%0,%1,%2,%3};"
        : "+f"(c[0]), "+f"(c[1]), "+f"(c[2]), "+f"(c[3])
        : "r"(a[0]), "r"(a[1]), "r"(a[2]), "r"(a[3]), "r"(b0), "r"(b1));
}
__device__ __forceinline__ void cpa16(uint32_t dst, const float* src) {
    asm volatile("cp.async.cg.shared.global [%0], [%1], 16;" :: "r"(dst), "l"(src));
}
#define CPA_COMMIT() asm volatile("cp.async.commit_group;" ::: "memory")
#define CPA_WAIT0()  asm volatile("cp.async.wait_group 0;" ::: "memory")
__device__ __forceinline__ void barg(int id) {
    asm volatile("bar.sync %0, 128;" :: "r"(id) : "memory");
}

// ---------------- main attention kernel ----------------
__global__ void __launch_bounds__(NTH, 2)
attn_mma_kernel(const float* __restrict__ q, const float* __restrict__ k,
                const float* __restrict__ v, float* __restrict__ out,
                float* __restrict__ attn)
{
    extern __shared__ char smem[];
    const uint32_t sb = s2u(smem);
    const int tid = threadIdx.x;
    const int w = tid >> 5, lane = tid & 31;
    const int wr = w >> 1;       // row block (16 rows)
    const int wc = w & 1;        // key-half group (32 keys)
    const int gtid = ((w >> 1) << 5) + lane;   // 0..127 within key-half group
    const int gbar = wc + 1;                   // named barrier id for this group
    const int quad = lane >> 2, qlane = lane & 3;
    const int qt = blockIdx.x, b = blockIdx.y;
    const int qbase = qt * TQ;

    // ---- load Q tile -> bf16 hi/lo smem ----
    {
        const float* qg = q + ((size_t)(b * SS + qbase)) * DDIM;
        #pragma unroll
        for (int it = 0; it < 4; ++it) {
            int idx = tid + it * NTH;
            int row = idx >> 4, d4 = (idx & 15) << 2;
            float4 qv = *(const float4*)(qg + row * DDIM + d4);
            uint32_t h01, l01, h23, l23;
            split2(qv.x, qv.y, h01, l01);
            split2(qv.z, qv.w, h23, l23);
            *(uint2*)(smem + OQHI + row * RS + d4 * 2) = make_uint2(h01, h23);
            *(uint2*)(smem + OQLO + row * RS + d4 * 2) = make_uint2(l01, l23);
        }
    }

    // ---- prefetch raw K/V tile 0 via cp.async (per key-half group) ----
    {
        const float* kg = k + ((size_t)(b * SS)) * DDIM;
        const float* vg = v + ((size_t)(b * SS)) * DDIM;
        #pragma unroll
        for (int it = 0; it < 4; ++it) {
            int idx = (wc << 9) + gtid + (it << 7);   // this group's 32-row half
            cpa16(sb + ORAWK + idx * 16, kg + idx * 4);
            cpa16(sb + ORAWV + idx * 16, vg + idx * 4);
        }
        CPA_COMMIT();
    }
    __syncthreads();   // Q visibility to all warps

    // ---- Q fragments (registers, whole CTA lifetime) ----
    uint32_t qh[4][4], ql[4][4];
    {
        uint32_t arow = (uint32_t)(wr * 16 + (lane & 15)) * RS + (uint32_t)(lane >> 4) * 16;
        #pragma unroll
        for (int ks = 0; ks < 4; ++ks) {
            ldm4(qh[ks][0], qh[ks][1], qh[ks][2], qh[ks][3], sb + OQHI + arow + ks * 32);
            ldm4(ql[ks][0], ql[ks][1], ql[ks][2], ql[ks][3], sb + OQLO + arow + ks * 32);
        }
    }

    float O[8][4];
    #pragma unroll
    for (int j = 0; j < 8; ++j)
        #pragma unroll
        for (int i = 0; i < 4; ++i) O[j][i] = 0.f;
    float lsum0 = 0.f, lsum1 = 0.f;
    const float CEXP = 0.18033688011112042f;  // (1/8)*log2(e)

    uint32_t kaddr = sb + (uint32_t)(wc * 32 + ((lane >> 4) << 3) + (lane & 7)) * RS
                        + (uint32_t)((lane >> 3) & 1) * 16;
    uint32_t vaddr = sb + (uint32_t)(wc * 32 + (((lane >> 3) & 1) << 3) + (lane & 7)) * RS
                        + (uint32_t)(lane >> 4) * 16;

    float* arow0 = attn + ((size_t)(b * SS + qbase + wr * 16 + quad)) * SS + wc * 32 + 2 * qlane;
    float* arow1 = arow0 + 8 * (size_t)SS;

    for (int kt = 0; kt < NKT; ++kt) {
        const int kbase = kt * TK;
        CPA_WAIT0();
        barg(gbar);   // group-local: raw(kt) visible; group's PV reads of kt-1 done

        // ---- convert this group's raw half f32 -> bf16 hi/lo tiles ----
        #pragma unroll
        for (int it = 0; it < 4; ++it) {
            int idx = (wc << 9) + gtid + (it << 7);
            int row = idx >> 4, d4 = (idx & 15) << 2;
            float4 kv = *(const float4*)(smem + ORAWK + idx * 16);
            uint32_t h01, l01, h23, l23;
            split2(kv.x, kv.y, h01, l01);
            split2(kv.z, kv.w, h23, l23);
            *(uint2*)(smem + OKHI + row * RS + d4 * 2) = make_uint2(h01, h23);
            *(uint2*)(smem + OKLO + row * RS + d4 * 2) = make_uint2(l01, l23);
            float4 vv = *(const float4*)(smem + ORAWV + idx * 16);
            split2(vv.x, vv.y, h01, l01);
            split2(vv.z, vv.w, h23, l23);
            *(uint2*)(smem + OVHI + row * RS + d4 * 2) = make_uint2(h01, h23);
            *(uint2*)(smem + OVLO + row * RS + d4 * 2) = make_uint2(l01, l23);
        }
        barg(gbar);   // group-local: bf16 half-tiles ready

        // ---- prefetch next tile's raw K/V for this group (overlaps MMA) ----
        if (kt + 1 < NKT) {
            const float* kg = k + ((size_t)(b * SS + kbase + TK)) * DDIM;
            const float* vg = v + ((size_t)(b * SS + kbase + TK)) * DDIM;
            #pragma unroll
            for (int it = 0; it < 4; ++it) {
                int idx = (wc << 9) + gtid + (it << 7);
                cpa16(sb + ORAWK + idx * 16, kg + idx * 4);
                cpa16(sb + ORAWV + idx * 16, vg + idx * 4);
            }
            CPA_COMMIT();
        }

        // ---- S = QK^T, 3-term split, ldmatrix software-pipelined ----
        float c[4][4];
        #pragma unroll
        for (int j = 0; j < 4; ++j)
            #pragma unroll
            for (int i = 0; i < 4; ++i) c[j][i] = 0.f;

        {
            uint32_t cbh[4], cbl[4], pbh[4], pbl[4];
            ldm4(cbh[0], cbh[1], cbh[2], cbh[3], kaddr + OKHI);
            ldm4(cbl[0], cbl[1], cbl[2], cbl[3], kaddr + OKLO);
            #pragma unroll
            for (int gi = 0; gi < 8; ++gi) {
                int ks = gi >> 1, half = gi & 1;
                if (gi < 7) {
                    int ksn = (gi + 1) >> 1, hn = (gi + 1) & 1;
                    uint32_t offn = (uint32_t)ksn * 32 + (uint32_t)hn * (16 * RS);
                    ldm4(pbh[0], pbh[1], pbh[2], pbh[3], kaddr + OKHI + offn);
                    ldm4(pbl[0], pbl[1], pbl[2], pbl[3], kaddr + OKLO + offn);
                }
                int j0 = 2 * half;
                mma16816(c[j0], qh[ks], cbh[0], cbh[1]);
                mma16816(c[j0], qh[ks], cbl[0], cbl[1]);
                mma16816(c[j0], ql[ks], cbh[0], cbh[1]);
                mma16816(c[j0 + 1], qh[ks], cbh[2], cbh[3]);
                mma16816(c[j0 + 1], qh[ks], cbl[2], cbl[3]);
                mma16816(c[j0 + 1], ql[ks], cbh[2], cbh[3]);
                #pragma unroll
                for (int t = 0; t < 4; ++t) { cbh[t] = pbh[t]; cbl[t] = pbl[t]; }
            }
        }

        // ---- exp (overwrite c with e), attn STG (unnormalized), row sums ----
        #pragma unroll
        for (int j = 0; j < 4; ++j) {
            #pragma unroll
            for (int i = 0; i < 4; ++i) c[j][i] = exp2f(c[j][i] * CEXP);
            lsum0 += c[j][0] + c[j][1];
            lsum1 += c[j][2] + c[j][3];
            float2 e01 = make_float2(c[j][0], c[j][1]);
            float2 e23 = make_float2(c[j][2], c[j][3]);
            *(float2*)(arow0 + kbase + 8 * j) = e01;
            *(float2*)(arow1 + kbase + 8 * j) = e23;
        }

        // ---- O += P V, 3-term split, ldmatrix.trans software-pipelined ----
        {
            uint32_t ah[4], al[4];
            uint32_t cvh[4], cvl[4], pvh[4], pvl[4];
            ldm4t(cvh[0], cvh[1], cvh[2], cvh[3], vaddr + OVHI);
            ldm4t(cvl[0], cvl[1], cvl[2], cvl[3], vaddr + OVLO);
            #pragma unroll
            for (int g = 0; g < 8; ++g) {
                if ((g & 3) == 0) {
                    int t2 = (g >> 2) << 1;
                    ah[0] = packbf(c[t2][0], c[t2][1]);
                    ah[1] = packbf(c[t2][2], c[t2][3]);
                    ah[2] = packbf(c[t2 + 1][0], c[t2 + 1][1]);
                    ah[3] = packbf(c[t2 + 1][2], c[t2 + 1][3]);
                    #pragma unroll
                    for (int i = 0; i < 4; ++i) {
                        int jt = t2 + (i >> 1);
                        int bbase = (i & 1) * 2;
                        float flo = c[jt][bbase]     - __uint_as_float(ah[i] << 16);
                        float fhi = c[jt][bbase + 1] - __uint_as_float(ah[i] & 0xFFFF0000u);
                        al[i] = packbf(flo, fhi);
                    }
                }
                if (g < 7) {
                    int gn = g + 1;
                    uint32_t offn = ((uint32_t)(gn >> 2)) * (16 * RS) + (uint32_t)(gn & 3) * 32;
                    ldm4t(pvh[0], pvh[1], pvh[2], pvh[3], vaddr + OVHI + offn);
                    ldm4t(pvl[0], pvl[1], pvl[2], pvl[3], vaddr + OVLO + offn);
                }
                int m = g & 3;
                mma16816(O[2 * m],     ah, cvh[0], cvh[1]);
                mma16816(O[2 * m],     ah, cvl[0], cvl[1]);
                mma16816(O[2 * m],     al, cvh[0], cvh[1]);
                mma16816(O[2 * m + 1], ah, cvh[2], cvh[3]);
                mma16816(O[2 * m + 1], ah, cvl[2], cvl[3]);
                mma16816(O[2 * m + 1], al, cvh[2], cvh[3]);
                #pragma unroll
                for (int t = 0; t < 4; ++t) { cvh[t] = pvh[t]; cvl[t] = pvl[t]; }
            }
        }
    }

    // ---- row-sum reduction across quad lanes ----
    lsum0 += __shfl_xor_sync(0xFFFFFFFFu, lsum0, 1);
    lsum0 += __shfl_xor_sync(0xFFFFFFFFu, lsum0, 2);
    lsum1 += __shfl_xor_sync(0xFFFFFFFFu, lsum1, 1);
    lsum1 += __shfl_xor_sync(0xFFFFFFFFu, lsum1, 2);

    float* lbuf = (float*)(smem + OLBUF);
    float* linv = (float*)(smem + OLINV);
    float* ored = (float*)(smem + ORED);

    if (qlane == 0) {
        lbuf[wc * 64 + wr * 16 + quad]     = lsum0;
        lbuf[wc * 64 + wr * 16 + quad + 8] = lsum1;
    }
    if (wc == 1) {
        #pragma unroll
        for (int j = 0; j < 8; ++j) {
            *(float2*)(ored + (wr * 16 + quad) * 68 + 8 * j + 2 * qlane)     = make_float2(O[j][0], O[j][1]);
            *(float2*)(ored + (wr * 16 + quad + 8) * 68 + 8 * j + 2 * qlane) = make_float2(O[j][2], O[j][3]);
        }
    }
    __syncthreads();
    if (tid < 64) {
        float s = lbuf[tid] + lbuf[64 + tid];
        linv[tid] = 1.0f / s;
    }
    __syncthreads();

    // ---- O epilogue: reduce halves, normalize, store ----
    if (wc == 0) {
        int r0 = wr * 16 + quad, r1 = r0 + 8;
        float inv0 = linv[r0], inv1 = linv[r1];
        float* op0 = out + ((size_t)(b * SS + qbase + r0)) * DDIM + 2 * qlane;
        float* op1 = out + ((size_t)(b * SS + qbase + r1)) * DDIM + 2 * qlane;
        #pragma unroll
        for (int j = 0; j < 8; ++j) {
            float2 p01 = *(float2*)(ored + r0 * 68 + 8 * j + 2 * qlane);
            float2 p23 = *(float2*)(ored + r1 * 68 + 8 * j + 2 * qlane);
            *(float2*)(op0 + 8 * j) = make_float2((O[j][0] + p01.x) * inv0, (O[j][1] + p01.y) * inv0);
            *(float2*)(op1 + 8 * j) = make_float2((O[j][2] + p23.x) * inv1, (O[j][3] + p23.y) * inv1);
        }
    }

    // ---- fused attn normalize tail (reverse order: hottest L2 lines first) ----
    {
        float4* abase = (float4*)(attn + ((size_t)(b * SS + qbase)) * SS);
        #pragma unroll 8
        for (int it = 127; it >= 0; --it) {
            int idx = tid + it * NTH;       // 0..32767 float4s
            int row = idx >> 9;             // 512 float4 per row
            int c4  = idx & 511;
            float inv = linv[row];
            float4* p = abase + (size_t)row * (SS / 4) + c4;
            float4 vv = *p;
            vv.x *= inv; vv.y *= inv; vv.z *= inv; vv.w *= inv;
            *p = vv;
        }
    }
}

extern "C" void kernel_launch(void* const* d_in, const int* in_sizes, int n_in,
                              void* d_out, int out_size)
{
    const float* q = (const float*)d_in[0];
    const float* k = (const float*)d_in[1];
    const float* v = (const float*)d_in[2];
    float* out  = (float*)d_out;
    float* attn = out + (size_t)BB * SS * DDIM;

    cudaFuncSetAttribute(attn_mma_kernel,
                         cudaFuncAttributeMaxDynamicSharedMemorySize, SMEMSZ);

    dim3 grid(SS / TQ, BB);
    attn_mma_kernel<<<grid, NTH, SMEMSZ>>>(q, k, v, out, attn);
}

// round 8
// speedup vs baseline: 1.1136x; 1.1136x over previous
#include <cuda_runtime.h>
#include <cstdint>

#define BB 32
#define SS 2048
#define DDIM 64
#define TQ 64
#define TK 64
#define NKT 32
#define NTH 256

// bf16 tile row stride: 72 elems = 144 bytes (16B-aligned, ldmatrix conflict-free)
#define RS 144
// smem byte offsets
#define OQHI 0u
#define OQLO 9216u
#define OKHI 18432u
#define OKLO 27648u
#define OVHI 36864u
#define OVLO 46080u
#define ORAWK 55296u          // raw f32 K stage (16 KB)
#define ORAWV 71680u          // raw f32 V stage (16 KB)
#define SMEMSZ 88064u
// epilogue reduce area reuses the Q region [0, 18432)
#define ORED  0u        // fp32 [64][68] O partials
#define OLBUF 17408u    // fp32 [128] row-sum partials
#define OLINV 17920u    // fp32 [64] inverse row sums

// ---------------- helpers ----------------
__device__ __forceinline__ uint32_t s2u(const void* p) {
    uint32_t a;
    asm("{ .reg .u64 t; cvta.to.shared.u64 t, %1; cvt.u32.u64 %0, t; }" : "=r"(a) : "l"(p));
    return a;
}
__device__ __forceinline__ void split2(float a, float b, uint32_t& hi, uint32_t& lo) {
    uint32_t h;
    asm("cvt.rn.bf16x2.f32 %0, %1, %2;" : "=r"(h) : "f"(b), "f"(a));
    float fa = __uint_as_float(h << 16);
    float fb = __uint_as_float(h & 0xFFFF0000u);
    float la = a - fa, lb = b - fb;
    asm("cvt.rn.bf16x2.f32 %0, %1, %2;" : "=r"(lo) : "f"(lb), "f"(la));
    hi = h;
}
__device__ __forceinline__ uint32_t packbf(float lo_e, float hi_e) {
    uint32_t r;
    asm("cvt.rn.bf16x2.f32 %0, %1, %2;" : "=r"(r) : "f"(hi_e), "f"(lo_e));
    return r;
}
__device__ __forceinline__ void ldm4(uint32_t& r0, uint32_t& r1, uint32_t& r2, uint32_t& r3, uint32_t a) {
    asm volatile("ldmatrix.sync.aligned.m8n8.x4.shared.b16 {%0,%1,%2,%3}, [%4];"
                 : "=r"(r0), "=r"(r1), "=r"(r2), "=r"(r3) : "r"(a));
}
__device__ __forceinline__ void ldm4t(uint32_t& r0, uint32_t& r1, uint32_t& r2, uint32_t& r3, uint32_t a) {
    asm volatile("ldmatrix.sync.aligned.m8n8.x4.trans.shared.b16 {%0,%1,%2,%3}, [%4];"
                 : "=r"(r0), "=r"(r1), "=r"(r2), "=r"(r3) : "r"(a));
}
__device__ __forceinline__ void mma16816(float* c, const uint32_t* a, uint32_t b0, uint32_t b1) {
    asm volatile(
        "mma.sync.aligned.m16n8k16.row.col.f32.bf16.bf16.f32 "
        "{%0,%1,%2,%3}, {%4,%5,%6,%7}, {%8,%9}, {%0,%1,%2,%3};"
        : "+f"(c[0]), "+f"(c[1]), "+f"(c[2]), "+f"(c[3])
        : "r"(a[0]), "r"(a[1]), "r"(a[2]), "r"(a[3]), "r"(b0), "r"(b1));
}
__device__ __forceinline__ void cpa16(uint32_t dst, const float* src) {
    asm volatile("cp.async.cg.shared.global [%0], [%1], 16;" :: "r"(dst), "l"(src));
}
#define CPA_COMMIT() asm volatile("cp.async.commit_group;" ::: "memory")
#define CPA_WAIT0()  asm volatile("cp.async.wait_group 0;" ::: "memory")

// ---------------- main attention kernel ----------------
__global__ void __launch_bounds__(NTH, 2)
attn_mma_kernel(const float* __restrict__ q, const float* __restrict__ k,
                const float* __restrict__ v, float* __restrict__ out,
                float* __restrict__ attn)
{
    extern __shared__ char smem[];
    const uint32_t sb = s2u(smem);
    const int tid = threadIdx.x;
    const int w = tid >> 5, lane = tid & 31;
    const int wr = w >> 1;       // row block (16 rows)
    const int wc = w & 1;        // key-half (32 keys)
    const int quad = lane >> 2, qlane = lane & 3;
    const int qt = blockIdx.x, b = blockIdx.y;
    const int qbase = qt * TQ;

    // ---- load Q tile -> bf16 hi/lo smem ----
    {
        const float* qg = q + ((size_t)(b * SS + qbase)) * DDIM;
        #pragma unroll
        for (int it = 0; it < 4; ++it) {
            int idx = tid + it * NTH;
            int row = idx >> 4, d4 = (idx & 15) << 2;
            float4 qv = *(const float4*)(qg + row * DDIM + d4);
            uint32_t h01, l01, h23, l23;
            split2(qv.x, qv.y, h01, l01);
            split2(qv.z, qv.w, h23, l23);
            *(uint2*)(smem + OQHI + row * RS + d4 * 2) = make_uint2(h01, h23);
            *(uint2*)(smem + OQLO + row * RS + d4 * 2) = make_uint2(l01, l23);
        }
    }

    // ---- prefetch raw K/V tile 0 via cp.async ----
    {
        const float* kg = k + ((size_t)(b * SS)) * DDIM;
        const float* vg = v + ((size_t)(b * SS)) * DDIM;
        #pragma unroll
        for (int it = 0; it < 4; ++it) {
            int idx = tid + it * NTH;
            cpa16(sb + ORAWK + idx * 16, kg + idx * 4);
            cpa16(sb + ORAWV + idx * 16, vg + idx * 4);
        }
        CPA_COMMIT();
    }
    __syncthreads();

    // ---- Q fragments (registers, whole CTA lifetime) ----
    uint32_t qh[4][4], ql[4][4];
    {
        uint32_t arow = (uint32_t)(wr * 16 + (lane & 15)) * RS + (uint32_t)(lane >> 4) * 16;
        #pragma unroll
        for (int ks = 0; ks < 4; ++ks) {
            ldm4(qh[ks][0], qh[ks][1], qh[ks][2], qh[ks][3], sb + OQHI + arow + ks * 32);
            ldm4(ql[ks][0], ql[ks][1], ql[ks][2], ql[ks][3], sb + OQLO + arow + ks * 32);
        }
    }

    float O[8][4];
    #pragma unroll
    for (int j = 0; j < 8; ++j)
        #pragma unroll
        for (int i = 0; i < 4; ++i) O[j][i] = 0.f;
    float lsum0 = 0.f, lsum1 = 0.f;
    const float CEXP = 0.18033688011112042f;  // (1/8)*log2(e)

    uint32_t kaddr = sb + (uint32_t)(wc * 32 + ((lane >> 4) << 3) + (lane & 7)) * RS
                        + (uint32_t)((lane >> 3) & 1) * 16;
    uint32_t vaddr = sb + (uint32_t)(wc * 32 + (((lane >> 3) & 1) << 3) + (lane & 7)) * RS
                        + (uint32_t)(lane >> 4) * 16;

    float* arow0 = attn + ((size_t)(b * SS + qbase + wr * 16 + quad)) * SS + wc * 32 + 2 * qlane;
    float* arow1 = arow0 + 8 * (size_t)SS;

    for (int kt = 0; kt < NKT; ++kt) {
        const int kbase = kt * TK;
        CPA_WAIT0();
        __syncthreads();   // raw(kt) visible to all; PV reads of kt-1 done

        // ---- convert raw smem f32 -> bf16 hi/lo tiles ----
        #pragma unroll
        for (int it = 0; it < 4; ++it) {
            int idx = tid + it * NTH;
            int row = idx >> 4, d4 = (idx & 15) << 2;
            float4 kv = *(const float4*)(smem + ORAWK + idx * 16);
            uint32_t h01, l01, h23, l23;
            split2(kv.x, kv.y, h01, l01);
            split2(kv.z, kv.w, h23, l23);
            *(uint2*)(smem + OKHI + row * RS + d4 * 2) = make_uint2(h01, h23);
            *(uint2*)(smem + OKLO + row * RS + d4 * 2) = make_uint2(l01, l23);
            float4 vv = *(const float4*)(smem + ORAWV + idx * 16);
            split2(vv.x, vv.y, h01, l01);
            split2(vv.z, vv.w, h23, l23);
            *(uint2*)(smem + OVHI + row * RS + d4 * 2) = make_uint2(h01, h23);
            *(uint2*)(smem + OVLO + row * RS + d4 * 2) = make_uint2(l01, l23);
        }
        __syncthreads();

        // ---- prefetch next tile's raw K/V (overlaps with MMA phase) ----
        if (kt + 1 < NKT) {
            const float* kg = k + ((size_t)(b * SS + kbase + TK)) * DDIM;
            const float* vg = v + ((size_t)(b * SS + kbase + TK)) * DDIM;
            #pragma unroll
            for (int it = 0; it < 4; ++it) {
                int idx = tid + it * NTH;
                cpa16(sb + ORAWK + idx * 16, kg + idx * 4);
                cpa16(sb + ORAWV + idx * 16, vg + idx * 4);
            }
            CPA_COMMIT();
        }

        // ---- S = QK^T, 3-term split, ldmatrix pipelined, chains interleaved ----
        float c[4][4];
        #pragma unroll
        for (int j = 0; j < 4; ++j)
            #pragma unroll
            for (int i = 0; i < 4; ++i) c[j][i] = 0.f;

        {
            uint32_t cbh[4], cbl[4], pbh[4], pbl[4];
            ldm4(cbh[0], cbh[1], cbh[2], cbh[3], kaddr + OKHI);
            ldm4(cbl[0], cbl[1], cbl[2], cbl[3], kaddr + OKLO);
            #pragma unroll
            for (int gi = 0; gi < 8; ++gi) {
                int ks = gi >> 1, half = gi & 1;
                if (gi < 7) {
                    int ksn = (gi + 1) >> 1, hn = (gi + 1) & 1;
                    uint32_t offn = (uint32_t)ksn * 32 + (uint32_t)hn * (16 * RS);
                    ldm4(pbh[0], pbh[1], pbh[2], pbh[3], kaddr + OKHI + offn);
                    ldm4(pbl[0], pbl[1], pbl[2], pbl[3], kaddr + OKLO + offn);
                }
                int j0 = 2 * half;
                // interleaved: alternate the two independent accumulators
                mma16816(c[j0],     qh[ks], cbh[0], cbh[1]);
                mma16816(c[j0 + 1], qh[ks], cbh[2], cbh[3]);
                mma16816(c[j0],     qh[ks], cbl[0], cbl[1]);
                mma16816(c[j0 + 1], qh[ks], cbl[2], cbl[3]);
                mma16816(c[j0],     ql[ks], cbh[0], cbh[1]);
                mma16816(c[j0 + 1], ql[ks], cbh[2], cbh[3]);
                #pragma unroll
                for (int t = 0; t < 4; ++t) { cbh[t] = pbh[t]; cbl[t] = pbl[t]; }
            }
        }

        // ---- exp (overwrite c with e), attn STG (unnormalized), row sums ----
        #pragma unroll
        for (int j = 0; j < 4; ++j) {
            #pragma unroll
            for (int i = 0; i < 4; ++i) c[j][i] = exp2f(c[j][i] * CEXP);
            lsum0 += c[j][0] + c[j][1];
            lsum1 += c[j][2] + c[j][3];
            float2 e01 = make_float2(c[j][0], c[j][1]);
            float2 e23 = make_float2(c[j][2], c[j][3]);
            *(float2*)(arow0 + kbase + 8 * j) = e01;
            *(float2*)(arow1 + kbase + 8 * j) = e23;
        }

        // ---- O += P V, 3-term split, chains interleaved ----
        #pragma unroll
        for (int ks2 = 0; ks2 < 2; ++ks2) {
            int t2 = 2 * ks2;
            uint32_t ah[4], al[4];
            ah[0] = packbf(c[t2][0], c[t2][1]);
            ah[1] = packbf(c[t2][2], c[t2][3]);
            ah[2] = packbf(c[t2 + 1][0], c[t2 + 1][1]);
            ah[3] = packbf(c[t2 + 1][2], c[t2 + 1][3]);
            #pragma unroll
            for (int i = 0; i < 4; ++i) {
                int jt = t2 + (i >> 1);
                int bbase = (i & 1) * 2;
                float flo = c[jt][bbase]     - __uint_as_float(ah[i] << 16);
                float fhi = c[jt][bbase + 1] - __uint_as_float(ah[i] & 0xFFFF0000u);
                al[i] = packbf(flo, fhi);
            }
            uint32_t va = vaddr + OVHI + (uint32_t)ks2 * (16 * RS);
            uint32_t vb = vaddr + OVLO + (uint32_t)ks2 * (16 * RS);
            #pragma unroll
            for (int m = 0; m < 4; ++m) {
                uint32_t bh0, bh1, bh2, bh3, bl0, bl1, bl2, bl3;
                ldm4t(bh0, bh1, bh2, bh3, va + m * 32);
                ldm4t(bl0, bl1, bl2, bl3, vb + m * 32);
                // interleaved: alternate the two independent accumulators
                mma16816(O[2 * m],     ah, bh0, bh1);
                mma16816(O[2 * m + 1], ah, bh2, bh3);
                mma16816(O[2 * m],     ah, bl0, bl1);
                mma16816(O[2 * m + 1], ah, bl2, bl3);
                mma16816(O[2 * m],     al, bh0, bh1);
                mma16816(O[2 * m + 1], al, bh2, bh3);
            }
        }
    }

    // ---- row-sum reduction across quad lanes ----
    lsum0 += __shfl_xor_sync(0xFFFFFFFFu, lsum0, 1);
    lsum0 += __shfl_xor_sync(0xFFFFFFFFu, lsum0, 2);
    lsum1 += __shfl_xor_sync(0xFFFFFFFFu, lsum1, 1);
    lsum1 += __shfl_xor_sync(0xFFFFFFFFu, lsum1, 2);

    float* lbuf = (float*)(smem + OLBUF);
    float* linv = (float*)(smem + OLINV);
    float* ored = (float*)(smem + ORED);

    if (qlane == 0) {
        lbuf[wc * 64 + wr * 16 + quad]     = lsum0;
        lbuf[wc * 64 + wr * 16 + quad + 8] = lsum1;
    }
    if (wc == 1) {
        #pragma unroll
        for (int j = 0; j < 8; ++j) {
            *(float2*)(ored + (wr * 16 + quad) * 68 + 8 * j + 2 * qlane)     = make_float2(O[j][0], O[j][1]);
            *(float2*)(ored + (wr * 16 + quad + 8) * 68 + 8 * j + 2 * qlane) = make_float2(O[j][2], O[j][3]);
        }
    }
    __syncthreads();
    if (tid < 64) {
        float s = lbuf[tid] + lbuf[64 + tid];
        linv[tid] = 1.0f / s;
    }
    __syncthreads();

    // ---- O epilogue: reduce halves, normalize, store ----
    if (wc == 0) {
        int r0 = wr * 16 + quad, r1 = r0 + 8;
        float inv0 = linv[r0], inv1 = linv[r1];
        float* op0 = out + ((size_t)(b * SS + qbase + r0)) * DDIM + 2 * qlane;
        float* op1 = out + ((size_t)(b * SS + qbase + r1)) * DDIM + 2 * qlane;
        #pragma unroll
        for (int j = 0; j < 8; ++j) {
            float2 p01 = *(float2*)(ored + r0 * 68 + 8 * j + 2 * qlane);
            float2 p23 = *(float2*)(ored + r1 * 68 + 8 * j + 2 * qlane);
            *(float2*)(op0 + 8 * j) = make_float2((O[j][0] + p01.x) * inv0, (O[j][1] + p01.y) * inv0);
            *(float2*)(op1 + 8 * j) = make_float2((O[j][2] + p23.x) * inv1, (O[j][3] + p23.y) * inv1);
        }
    }

    // ---- fused attn normalize tail (L2-resident RMW of own rows) ----
    {
        float4* abase = (float4*)(attn + ((size_t)(b * SS + qbase)) * SS);
        #pragma unroll 8
        for (int it = 0; it < 128; ++it) {
            int idx = tid + it * NTH;       // 0..32767 float4s
            int row = idx >> 9;             // 512 float4 per row
            int c4  = idx & 511;
            float inv = linv[row];
            float4* p = abase + (size_t)row * (SS / 4) + c4;
            float4 vv = *p;
            vv.x *= inv; vv.y *= inv; vv.z *= inv; vv.w *= inv;
            *p = vv;
        }
    }
}

extern "C" void kernel_launch(void* const* d_in, const int* in_sizes, int n_in,
                              void* d_out, int out_size)
{
    const float* q = (const float*)d_in[0];
    const float* k = (const float*)d_in[1];
    const float* v = (const float*)d_in[2];
    float* out  = (float*)d_out;
    float* attn = out + (size_t)BB * SS * DDIM;

    cudaFuncSetAttribute(attn_mma_kernel,
                         cudaFuncAttributeMaxDynamicSharedMemorySize, SMEMSZ);

    dim3 grid(SS / TQ, BB);
    attn_mma_kernel<<<grid, NTH, SMEMSZ>>>(q, k, v, out, attn);
}

// round 9
// speedup vs baseline: 1.3000x; 1.1674x over previous
#include <cuda_runtime.h>
#include <cstdint>

#define BB 32
#define SS 2048
#define DDIM 64
#define TQ 64
#define TK 64
#define NKT 32
#define NTH 256

// fp16 tile row stride: 72 elems = 144 bytes (16B-aligned, ldmatrix conflict-free)
#define RS 144
// smem byte offsets
#define OQHI 0u
#define OQLO 9216u
#define OKHI 18432u
#define OVHI 27648u
#define ORAWK 36864u          // raw f32 K stage (16 KB)
#define ORAWV 53248u          // raw f32 V stage (16 KB)
#define SMEMSZ 69632u
// epilogue reduce area reuses the Q region [0, 18432)
#define ORED  0u        // fp32 [64][68] O partials
#define OLBUF 17408u    // fp32 [128] row-sum partials
#define OLINV 17920u    // fp32 [64] inverse row sums

// ---------------- helpers ----------------
__device__ __forceinline__ uint32_t s2u(const void* p) {
    uint32_t a;
    asm("{ .reg .u64 t; cvta.to.shared.u64 t, %1; cvt.u32.u64 %0, t; }" : "=r"(a) : "l"(p));
    return a;
}
// pack (a,b) -> fp16x2 (a in low half)
__device__ __forceinline__ void packh2(float a, float b, uint32_t& h) {
    asm("cvt.rn.f16x2.f32 %0, %1, %2;" : "=r"(h) : "f"(b), "f"(a));
}
__device__ __forceinline__ void unpackh2(uint32_t h, float& fa, float& fb) {
    asm("{ .reg .b16 x, y; mov.b32 {x, y}, %2; cvt.f32.f16 %0, x; cvt.f32.f16 %1, y; }"
        : "=f"(fa), "=f"(fb) : "r"(h));
}
// split pair (a,b) -> fp16x2 hi + fp16x2 residual lo
__device__ __forceinline__ void split2h(float a, float b, uint32_t& hi, uint32_t& lo) {
    packh2(a, b, hi);
    float fa, fb;
    unpackh2(hi, fa, fb);
    packh2(a - fa, b - fb, lo);
}
__device__ __forceinline__ void ldm4(uint32_t& r0, uint32_t& r1, uint32_t& r2, uint32_t& r3, uint32_t a) {
    asm volatile("ldmatrix.sync.aligned.m8n8.x4.shared.b16 {%0,%1,%2,%3}, [%4];"
                 : "=r"(r0), "=r"(r1), "=r"(r2), "=r"(r3) : "r"(a));
}
__device__ __forceinline__ void ldm4t(uint32_t& r0, uint32_t& r1, uint32_t& r2, uint32_t& r3, uint32_t a) {
    asm volatile("ldmatrix.sync.aligned.m8n8.x4.trans.shared.b16 {%0,%1,%2,%3}, [%4];"
                 : "=r"(r0), "=r"(r1), "=r"(r2), "=r"(r3) : "r"(a));
}
__device__ __forceinline__ void mma16816(float* c, const uint32_t* a, uint32_t b0, uint32_t b1) {
    asm volatile(
        "mma.sync.aligned.m16n8k16.row.col.f32.f16.f16.f32 "
        "{%0,%1,%2,%3}, {%4,%5,%6,%7}, {%8,%9}, {%0,%1,%2,%3};"
        : "+f"(c[0]), "+f"(c[1]), "+f"(c[2]), "+f"(c[3])
        : "r"(a[0]), "r"(a[1]), "r"(a[2]), "r"(a[3]), "r"(b0), "r"(b1));
}
__device__ __forceinline__ void cpa16(uint32_t dst, const float* src) {
    asm volatile("cp.async.cg.shared.global [%0], [%1], 16;" :: "r"(dst), "l"(src));
}
#define CPA_COMMIT() asm volatile("cp.async.commit_group;" ::: "memory")
#define CPA_WAIT0()  asm volatile("cp.async.wait_group 0;" ::: "memory")

// ---------------- main attention kernel ----------------
__global__ void __launch_bounds__(NTH, 2)
attn_mma_kernel(const float* __restrict__ q, const float* __restrict__ k,
                const float* __restrict__ v, float* __restrict__ out,
                float* __restrict__ attn)
{
    extern __shared__ char smem[];
    const uint32_t sb = s2u(smem);
    const int tid = threadIdx.x;
    const int w = tid >> 5, lane = tid & 31;
    const int wr = w >> 1;       // row block (16 rows)
    const int wc = w & 1;        // key-half (32 keys)
    const int quad = lane >> 2, qlane = lane & 3;
    const int qt = blockIdx.x, b = blockIdx.y;
    const int qbase = qt * TQ;

    // ---- load Q tile -> fp16 hi/lo smem ----
    {
        const float* qg = q + ((size_t)(b * SS + qbase)) * DDIM;
        #pragma unroll
        for (int it = 0; it < 4; ++it) {
            int idx = tid + it * NTH;
            int row = idx >> 4, d4 = (idx & 15) << 2;
            float4 qv = *(const float4*)(qg + row * DDIM + d4);
            uint32_t h01, l01, h23, l23;
            split2h(qv.x, qv.y, h01, l01);
            split2h(qv.z, qv.w, h23, l23);
            *(uint2*)(smem + OQHI + row * RS + d4 * 2) = make_uint2(h01, h23);
            *(uint2*)(smem + OQLO + row * RS + d4 * 2) = make_uint2(l01, l23);
        }
    }

    // ---- prefetch raw K/V tile 0 via cp.async ----
    {
        const float* kg = k + ((size_t)(b * SS)) * DDIM;
        const float* vg = v + ((size_t)(b * SS)) * DDIM;
        #pragma unroll
        for (int it = 0; it < 4; ++it) {
            int idx = tid + it * NTH;
            cpa16(sb + ORAWK + idx * 16, kg + idx * 4);
            cpa16(sb + ORAWV + idx * 16, vg + idx * 4);
        }
        CPA_COMMIT();
    }
    __syncthreads();

    // ---- Q fragments (registers, whole CTA lifetime) ----
    uint32_t qh[4][4], ql[4][4];
    {
        uint32_t arow = (uint32_t)(wr * 16 + (lane & 15)) * RS + (uint32_t)(lane >> 4) * 16;
        #pragma unroll
        for (int ks = 0; ks < 4; ++ks) {
            ldm4(qh[ks][0], qh[ks][1], qh[ks][2], qh[ks][3], sb + OQHI + arow + ks * 32);
            ldm4(ql[ks][0], ql[ks][1], ql[ks][2], ql[ks][3], sb + OQLO + arow + ks * 32);
        }
    }

    float O[8][4];
    #pragma unroll
    for (int j = 0; j < 8; ++j)
        #pragma unroll
        for (int i = 0; i < 4; ++i) O[j][i] = 0.f;
    float lsum0 = 0.f, lsum1 = 0.f;
    const float CEXP = 0.18033688011112042f;  // (1/8)*log2(e)

    uint32_t kaddr = sb + (uint32_t)(wc * 32 + ((lane >> 4) << 3) + (lane & 7)) * RS
                        + (uint32_t)((lane >> 3) & 1) * 16;
    uint32_t vaddr = sb + (uint32_t)(wc * 32 + (((lane >> 3) & 1) << 3) + (lane & 7)) * RS
                        + (uint32_t)(lane >> 4) * 16;

    float* arow0 = attn + ((size_t)(b * SS + qbase + wr * 16 + quad)) * SS + wc * 32 + 2 * qlane;
    float* arow1 = arow0 + 8 * (size_t)SS;

    for (int kt = 0; kt < NKT; ++kt) {
        const int kbase = kt * TK;
        CPA_WAIT0();
        __syncthreads();   // raw(kt) visible to all; PV reads of kt-1 done

        // ---- convert raw smem f32 -> fp16 hi tiles (K, V hi-only) ----
        #pragma unroll
        for (int it = 0; it < 4; ++it) {
            int idx = tid + it * NTH;
            int row = idx >> 4, d4 = (idx & 15) << 2;
            float4 kv = *(const float4*)(smem + ORAWK + idx * 16);
            uint32_t h01, h23;
            packh2(kv.x, kv.y, h01);
            packh2(kv.z, kv.w, h23);
            *(uint2*)(smem + OKHI + row * RS + d4 * 2) = make_uint2(h01, h23);
            float4 vv = *(const float4*)(smem + ORAWV + idx * 16);
            packh2(vv.x, vv.y, h01);
            packh2(vv.z, vv.w, h23);
            *(uint2*)(smem + OVHI + row * RS + d4 * 2) = make_uint2(h01, h23);
        }
        __syncthreads();

        // ---- prefetch next tile's raw K/V (overlaps with MMA phase) ----
        if (kt + 1 < NKT) {
            const float* kg = k + ((size_t)(b * SS + kbase + TK)) * DDIM;
            const float* vg = v + ((size_t)(b * SS + kbase + TK)) * DDIM;
            #pragma unroll
            for (int it = 0; it < 4; ++it) {
                int idx = tid + it * NTH;
                cpa16(sb + ORAWK + idx * 16, kg + idx * 4);
                cpa16(sb + ORAWV + idx * 16, vg + idx * 4);
            }
            CPA_COMMIT();
        }

        // ---- S = QK^T, 2-term fp16 split (q exact, K rounded), pipelined ----
        float c[4][4];
        #pragma unroll
        for (int j = 0; j < 4; ++j)
            #pragma unroll
            for (int i = 0; i < 4; ++i) c[j][i] = 0.f;

        {
            uint32_t cbh[4], pbh[4];
            ldm4(cbh[0], cbh[1], cbh[2], cbh[3], kaddr + OKHI);
            #pragma unroll
            for (int gi = 0; gi < 8; ++gi) {
                int ks = gi >> 1, half = gi & 1;
                if (gi < 7) {
                    int ksn = (gi + 1) >> 1, hn = (gi + 1) & 1;
                    uint32_t offn = (uint32_t)ksn * 32 + (uint32_t)hn * (16 * RS);
                    ldm4(pbh[0], pbh[1], pbh[2], pbh[3], kaddr + OKHI + offn);
                }
                int j0 = 2 * half;
                mma16816(c[j0],     qh[ks], cbh[0], cbh[1]);
                mma16816(c[j0 + 1], qh[ks], cbh[2], cbh[3]);
                mma16816(c[j0],     ql[ks], cbh[0], cbh[1]);
                mma16816(c[j0 + 1], ql[ks], cbh[2], cbh[3]);
                #pragma unroll
                for (int t = 0; t < 4; ++t) cbh[t] = pbh[t];
            }
        }

        // ---- exp (overwrite c with e), attn STG (unnormalized), row sums ----
        #pragma unroll
        for (int j = 0; j < 4; ++j) {
            #pragma unroll
            for (int i = 0; i < 4; ++i) c[j][i] = exp2f(c[j][i] * CEXP);
            lsum0 += c[j][0] + c[j][1];
            lsum1 += c[j][2] + c[j][3];
            float2 e01 = make_float2(c[j][0], c[j][1]);
            float2 e23 = make_float2(c[j][2], c[j][3]);
            *(float2*)(arow0 + kbase + 8 * j) = e01;
            *(float2*)(arow1 + kbase + 8 * j) = e23;
        }

        // ---- O += P V, 2-term fp16 split (P exact, V rounded) ----
        #pragma unroll
        for (int ks2 = 0; ks2 < 2; ++ks2) {
            int t2 = 2 * ks2;
            uint32_t ah[4], al[4];
            packh2(c[t2][0],     c[t2][1],     ah[0]);
            packh2(c[t2][2],     c[t2][3],     ah[1]);
            packh2(c[t2 + 1][0], c[t2 + 1][1], ah[2]);
            packh2(c[t2 + 1][2], c[t2 + 1][3], ah[3]);
            #pragma unroll
            for (int i = 0; i < 4; ++i) {
                int jt = t2 + (i >> 1);
                int bbase = (i & 1) * 2;
                float fa, fb;
                unpackh2(ah[i], fa, fb);
                packh2(c[jt][bbase] - fa, c[jt][bbase + 1] - fb, al[i]);
            }
            uint32_t va = vaddr + OVHI + (uint32_t)ks2 * (16 * RS);
            #pragma unroll
            for (int m = 0; m < 4; ++m) {
                uint32_t bh0, bh1, bh2, bh3;
                ldm4t(bh0, bh1, bh2, bh3, va + m * 32);
                mma16816(O[2 * m],     ah, bh0, bh1);
                mma16816(O[2 * m + 1], ah, bh2, bh3);
                mma16816(O[2 * m],     al, bh0, bh1);
                mma16816(O[2 * m + 1], al, bh2, bh3);
            }
        }
    }

    // ---- row-sum reduction across quad lanes ----
    lsum0 += __shfl_xor_sync(0xFFFFFFFFu, lsum0, 1);
    lsum0 += __shfl_xor_sync(0xFFFFFFFFu, lsum0, 2);
    lsum1 += __shfl_xor_sync(0xFFFFFFFFu, lsum1, 1);
    lsum1 += __shfl_xor_sync(0xFFFFFFFFu, lsum1, 2);

    float* lbuf = (float*)(smem + OLBUF);
    float* linv = (float*)(smem + OLINV);
    float* ored = (float*)(smem + ORED);

    if (qlane == 0) {
        lbuf[wc * 64 + wr * 16 + quad]     = lsum0;
        lbuf[wc * 64 + wr * 16 + quad + 8] = lsum1;
    }
    if (wc == 1) {
        #pragma unroll
        for (int j = 0; j < 8; ++j) {
            *(float2*)(ored + (wr * 16 + quad) * 68 + 8 * j + 2 * qlane)     = make_float2(O[j][0], O[j][1]);
            *(float2*)(ored + (wr * 16 + quad + 8) * 68 + 8 * j + 2 * qlane) = make_float2(O[j][2], O[j][3]);
        }
    }
    __syncthreads();
    if (tid < 64) {
        float s = lbuf[tid] + lbuf[64 + tid];
        linv[tid] = 1.0f / s;
    }
    __syncthreads();

    // ---- O epilogue: reduce halves, normalize, store ----
    if (wc == 0) {
        int r0 = wr * 16 + quad, r1 = r0 + 8;
        float inv0 = linv[r0], inv1 = linv[r1];
        float* op0 = out + ((size_t)(b * SS + qbase + r0)) * DDIM + 2 * qlane;
        float* op1 = out + ((size_t)(b * SS + qbase + r1)) * DDIM + 2 * qlane;
        #pragma unroll
        for (int j = 0; j < 8; ++j) {
            float2 p01 = *(float2*)(ored + r0 * 68 + 8 * j + 2 * qlane);
            float2 p23 = *(float2*)(ored + r1 * 68 + 8 * j + 2 * qlane);
            *(float2*)(op0 + 8 * j) = make_float2((O[j][0] + p01.x) * inv0, (O[j][1] + p01.y) * inv0);
            *(float2*)(op1 + 8 * j) = make_float2((O[j][2] + p23.x) * inv1, (O[j][3] + p23.y) * inv1);
        }
    }

    // ---- fused attn normalize tail (L2-resident RMW of own rows) ----
    {
        float4* abase = (float4*)(attn + ((size_t)(b * SS + qbase)) * SS);
        #pragma unroll 8
        for (int it = 0; it < 128; ++it) {
            int idx = tid + it * NTH;       // 0..32767 float4s
            int row = idx >> 9;             // 512 float4 per row
            int c4  = idx & 511;
            float inv = linv[row];
            float4* p = abase + (size_t)row * (SS / 4) + c4;
            float4 vv = *p;
            vv.x *= inv; vv.y *= inv; vv.z *= inv; vv.w *= inv;
            *p = vv;
        }
    }
}

extern "C" void kernel_launch(void* const* d_in, const int* in_sizes, int n_in,
                              void* d_out, int out_size)
{
    const float* q = (const float*)d_in[0];
    const float* k = (const float*)d_in[1];
    const float* v = (const float*)d_in[2];
    float* out  = (float*)d_out;
    float* attn = out + (size_t)BB * SS * DDIM;

    cudaFuncSetAttribute(attn_mma_kernel,
                         cudaFuncAttributeMaxDynamicSharedMemorySize, SMEMSZ);

    dim3 grid(SS / TQ, BB);
    attn_mma_kernel<<<grid, NTH, SMEMSZ>>>(q, k, v, out, attn);
}

// round 10
// speedup vs baseline: 1.3764x; 1.0587x over previous
#include <cuda_runtime.h>
#include <cstdint>

#define BB 32
#define SS 2048
#define DDIM 64
#define TQ 64
#define TK 64
#define NKT 32
#define NTH 256

// fp16 tile row stride: 72 elems = 144 bytes (16B-aligned, ldmatrix conflict-free)
#define RS 144
// smem byte offsets
#define OQHI 0u
#define OKHI 9216u
#define OVHI 18432u
#define ORAWK 27648u          // raw f32 K stage (16 KB)
#define ORAWV 44032u          // raw f32 V stage (16 KB)
#define SMEMSZ 60416u
// epilogue reduce area reuses the Q/K regions (dead after main loop)
#define ORED  0u        // fp32 [64][68] O partials
#define OLBUF 17408u    // fp32 [128] row-sum partials
#define OLINV 17920u    // fp32 [64] inverse row sums

// ---------------- helpers ----------------
__device__ __forceinline__ uint32_t s2u(const void* p) {
    uint32_t a;
    asm("{ .reg .u64 t; cvta.to.shared.u64 t, %1; cvt.u32.u64 %0, t; }" : "=r"(a) : "l"(p));
    return a;
}
// pack (a,b) -> fp16x2 (a in low half)
__device__ __forceinline__ void packh2(float a, float b, uint32_t& h) {
    asm("cvt.rn.f16x2.f32 %0, %1, %2;" : "=r"(h) : "f"(b), "f"(a));
}
__device__ __forceinline__ void ldm4(uint32_t& r0, uint32_t& r1, uint32_t& r2, uint32_t& r3, uint32_t a) {
    asm volatile("ldmatrix.sync.aligned.m8n8.x4.shared.b16 {%0,%1,%2,%3}, [%4];"
                 : "=r"(r0), "=r"(r1), "=r"(r2), "=r"(r3) : "r"(a));
}
__device__ __forceinline__ void ldm4t(uint32_t& r0, uint32_t& r1, uint32_t& r2, uint32_t& r3, uint32_t a) {
    asm volatile("ldmatrix.sync.aligned.m8n8.x4.trans.shared.b16 {%0,%1,%2,%3}, [%4];"
                 : "=r"(r0), "=r"(r1), "=r"(r2), "=r"(r3) : "r"(a));
}
__device__ __forceinline__ void mma16816(float* c, const uint32_t* a, uint32_t b0, uint32_t b1) {
    asm volatile(
        "mma.sync.aligned.m16n8k16.row.col.f32.f16.f16.f32 "
        "{%0,%1,%2,%3}, {%4,%5,%6,%7}, {%8,%9}, {%0,%1,%2,%3};"
        : "+f"(c[0]), "+f"(c[1]), "+f"(c[2]), "+f"(c[3])
        : "r"(a[0]), "r"(a[1]), "r"(a[2]), "r"(a[3]), "r"(b0), "r"(b1));
}
__device__ __forceinline__ void cpa16(uint32_t dst, const float* src) {
    asm volatile("cp.async.cg.shared.global [%0], [%1], 16;" :: "r"(dst), "l"(src));
}
#define CPA_COMMIT() asm volatile("cp.async.commit_group;" ::: "memory")
#define CPA_WAIT0()  asm volatile("cp.async.wait_group 0;" ::: "memory")

// ---------------- main attention kernel ----------------
__global__ void __launch_bounds__(NTH, 2)
attn_mma_kernel(const float* __restrict__ q, const float* __restrict__ k,
                const float* __restrict__ v, float* __restrict__ out,
                float* __restrict__ attn)
{
    extern __shared__ char smem[];
    const uint32_t sb = s2u(smem);
    const int tid = threadIdx.x;
    const int w = tid >> 5, lane = tid & 31;
    const int wr = w >> 1;       // row block (16 rows)
    const int wc = w & 1;        // key-half (32 keys)
    const int quad = lane >> 2, qlane = lane & 3;
    const int qt = blockIdx.x, b = blockIdx.y;
    const int qbase = qt * TQ;

    // ---- load Q tile -> fp16 smem ----
    {
        const float* qg = q + ((size_t)(b * SS + qbase)) * DDIM;
        #pragma unroll
        for (int it = 0; it < 4; ++it) {
            int idx = tid + it * NTH;
            int row = idx >> 4, d4 = (idx & 15) << 2;
            float4 qv = *(const float4*)(qg + row * DDIM + d4);
            uint32_t h01, h23;
            packh2(qv.x, qv.y, h01);
            packh2(qv.z, qv.w, h23);
            *(uint2*)(smem + OQHI + row * RS + d4 * 2) = make_uint2(h01, h23);
        }
    }

    // ---- prefetch raw K/V tile 0 via cp.async ----
    {
        const float* kg = k + ((size_t)(b * SS)) * DDIM;
        const float* vg = v + ((size_t)(b * SS)) * DDIM;
        #pragma unroll
        for (int it = 0; it < 4; ++it) {
            int idx = tid + it * NTH;
            cpa16(sb + ORAWK + idx * 16, kg + idx * 4);
            cpa16(sb + ORAWV + idx * 16, vg + idx * 4);
        }
        CPA_COMMIT();
    }
    __syncthreads();

    // ---- Q fragments (registers, whole CTA lifetime) ----
    uint32_t qh[4][4];
    {
        uint32_t arow = (uint32_t)(wr * 16 + (lane & 15)) * RS + (uint32_t)(lane >> 4) * 16;
        #pragma unroll
        for (int ks = 0; ks < 4; ++ks)
            ldm4(qh[ks][0], qh[ks][1], qh[ks][2], qh[ks][3], sb + OQHI + arow + ks * 32);
    }

    float O[8][4];
    #pragma unroll
    for (int j = 0; j < 8; ++j)
        #pragma unroll
        for (int i = 0; i < 4; ++i) O[j][i] = 0.f;
    float lsum0 = 0.f, lsum1 = 0.f;
    const float CEXP = 0.18033688011112042f;  // (1/8)*log2(e)

    uint32_t kaddr = sb + (uint32_t)(wc * 32 + ((lane >> 4) << 3) + (lane & 7)) * RS
                        + (uint32_t)((lane >> 3) & 1) * 16;
    uint32_t vaddr = sb + (uint32_t)(wc * 32 + (((lane >> 3) & 1) << 3) + (lane & 7)) * RS
                        + (uint32_t)(lane >> 4) * 16;

    float* arow0 = attn + ((size_t)(b * SS + qbase + wr * 16 + quad)) * SS + wc * 32 + 2 * qlane;
    float* arow1 = arow0 + 8 * (size_t)SS;

    for (int kt = 0; kt < NKT; ++kt) {
        const int kbase = kt * TK;
        CPA_WAIT0();
        __syncthreads();   // raw(kt) visible to all; PV reads of kt-1 done

        // ---- convert raw smem f32 -> fp16 tiles ----
        #pragma unroll
        for (int it = 0; it < 4; ++it) {
            int idx = tid + it * NTH;
            int row = idx >> 4, d4 = (idx & 15) << 2;
            float4 kv = *(const float4*)(smem + ORAWK + idx * 16);
            uint32_t h01, h23;
            packh2(kv.x, kv.y, h01);
            packh2(kv.z, kv.w, h23);
            *(uint2*)(smem + OKHI + row * RS + d4 * 2) = make_uint2(h01, h23);
            float4 vv = *(const float4*)(smem + ORAWV + idx * 16);
            packh2(vv.x, vv.y, h01);
            packh2(vv.z, vv.w, h23);
            *(uint2*)(smem + OVHI + row * RS + d4 * 2) = make_uint2(h01, h23);
        }
        __syncthreads();

        // ---- prefetch next tile's raw K/V (overlaps with MMA phase) ----
        if (kt + 1 < NKT) {
            const float* kg = k + ((size_t)(b * SS + kbase + TK)) * DDIM;
            const float* vg = v + ((size_t)(b * SS + kbase + TK)) * DDIM;
            #pragma unroll
            for (int it = 0; it < 4; ++it) {
                int idx = tid + it * NTH;
                cpa16(sb + ORAWK + idx * 16, kg + idx * 4);
                cpa16(sb + ORAWV + idx * 16, vg + idx * 4);
            }
            CPA_COMMIT();
        }

        // ---- S = QK^T, single-term fp16, ldmatrix pipelined ----
        float c[4][4];
        #pragma unroll
        for (int j = 0; j < 4; ++j)
            #pragma unroll
            for (int i = 0; i < 4; ++i) c[j][i] = 0.f;

        {
            uint32_t cbh[4], pbh[4];
            ldm4(cbh[0], cbh[1], cbh[2], cbh[3], kaddr + OKHI);
            #pragma unroll
            for (int gi = 0; gi < 8; ++gi) {
                int ks = gi >> 1, half = gi & 1;
                if (gi < 7) {
                    int ksn = (gi + 1) >> 1, hn = (gi + 1) & 1;
                    uint32_t offn = (uint32_t)ksn * 32 + (uint32_t)hn * (16 * RS);
                    ldm4(pbh[0], pbh[1], pbh[2], pbh[3], kaddr + OKHI + offn);
                }
                int j0 = 2 * half;
                mma16816(c[j0],     qh[ks], cbh[0], cbh[1]);
                mma16816(c[j0 + 1], qh[ks], cbh[2], cbh[3]);
                #pragma unroll
                for (int t = 0; t < 4; ++t) cbh[t] = pbh[t];
            }
        }

        // ---- exp (overwrite c with e), attn STG (unnormalized), row sums ----
        #pragma unroll
        for (int j = 0; j < 4; ++j) {
            #pragma unroll
            for (int i = 0; i < 4; ++i) c[j][i] = exp2f(c[j][i] * CEXP);
            lsum0 += c[j][0] + c[j][1];
            lsum1 += c[j][2] + c[j][3];
            float2 e01 = make_float2(c[j][0], c[j][1]);
            float2 e23 = make_float2(c[j][2], c[j][3]);
            *(float2*)(arow0 + kbase + 8 * j) = e01;
            *(float2*)(arow1 + kbase + 8 * j) = e23;
        }

        // ---- O += P V, single-term fp16 ----
        #pragma unroll
        for (int ks2 = 0; ks2 < 2; ++ks2) {
            int t2 = 2 * ks2;
            uint32_t ah[4];
            packh2(c[t2][0],     c[t2][1],     ah[0]);
            packh2(c[t2][2],     c[t2][3],     ah[1]);
            packh2(c[t2 + 1][0], c[t2 + 1][1], ah[2]);
            packh2(c[t2 + 1][2], c[t2 + 1][3], ah[3]);
            uint32_t va = vaddr + OVHI + (uint32_t)ks2 * (16 * RS);
            #pragma unroll
            for (int m = 0; m < 4; ++m) {
                uint32_t bh0, bh1, bh2, bh3;
                ldm4t(bh0, bh1, bh2, bh3, va + m * 32);
                mma16816(O[2 * m],     ah, bh0, bh1);
                mma16816(O[2 * m + 1], ah, bh2, bh3);
            }
        }
    }

    // ---- row-sum reduction across quad lanes ----
    lsum0 += __shfl_xor_sync(0xFFFFFFFFu, lsum0, 1);
    lsum0 += __shfl_xor_sync(0xFFFFFFFFu, lsum0, 2);
    lsum1 += __shfl_xor_sync(0xFFFFFFFFu, lsum1, 1);
    lsum1 += __shfl_xor_sync(0xFFFFFFFFu, lsum1, 2);

    float* lbuf = (float*)(smem + OLBUF);
    float* linv = (float*)(smem + OLINV);
    float* ored = (float*)(smem + ORED);

    if (qlane == 0) {
        lbuf[wc * 64 + wr * 16 + quad]     = lsum0;
        lbuf[wc * 64 + wr * 16 + quad + 8] = lsum1;
    }
    if (wc == 1) {
        #pragma unroll
        for (int j = 0; j < 8; ++j) {
            *(float2*)(ored + (wr * 16 + quad) * 68 + 8 * j + 2 * qlane)     = make_float2(O[j][0], O[j][1]);
            *(float2*)(ored + (wr * 16 + quad + 8) * 68 + 8 * j + 2 * qlane) = make_float2(O[j][2], O[j][3]);
        }
    }
    __syncthreads();
    if (tid < 64) {
        float s = lbuf[tid] + lbuf[64 + tid];
        linv[tid] = 1.0f / s;
    }
    __syncthreads();

    // ---- O epilogue: reduce halves, normalize, store ----
    if (wc == 0) {
        int r0 = wr * 16 + quad, r1 = r0 + 8;
        float inv0 = linv[r0], inv1 = linv[r1];
        float* op0 = out + ((size_t)(b * SS + qbase + r0)) * DDIM + 2 * qlane;
        float* op1 = out + ((size_t)(b * SS + qbase + r1)) * DDIM + 2 * qlane;
        #pragma unroll
        for (int j = 0; j < 8; ++j) {
            float2 p01 = *(float2*)(ored + r0 * 68 + 8 * j + 2 * qlane);
            float2 p23 = *(float2*)(ored + r1 * 68 + 8 * j + 2 * qlane);
            *(float2*)(op0 + 8 * j) = make_float2((O[j][0] + p01.x) * inv0, (O[j][1] + p01.y) * inv0);
            *(float2*)(op1 + 8 * j) = make_float2((O[j][2] + p23.x) * inv1, (O[j][3] + p23.y) * inv1);
        }
    }

    // ---- fused attn normalize tail (L2-resident RMW of own rows) ----
    {
        float4* abase = (float4*)(attn + ((size_t)(b * SS + qbase)) * SS);
        #pragma unroll 8
        for (int it = 0; it < 128; ++it) {
            int idx = tid + it * NTH;       // 0..32767 float4s
            int row = idx >> 9;             // 512 float4 per row
            int c4  = idx & 511;
            float inv = linv[row];
            float4* p = abase + (size_t)row * (SS / 4) + c4;
            float4 vv = *p;
            vv.x *= inv; vv.y *= inv; vv.z *= inv; vv.w *= inv;
            *p = vv;
        }
    }
}

extern "C" void kernel_launch(void* const* d_in, const int* in_sizes, int n_in,
                              void* d_out, int out_size)
{
    const float* q = (const float*)d_in[0];
    const float* k = (const float*)d_in[1];
    const float* v = (const float*)d_in[2];
    float* out  = (float*)d_out;
    float* attn = out + (size_t)BB * SS * DDIM;

    cudaFuncSetAttribute(attn_mma_kernel,
                         cudaFuncAttributeMaxDynamicSharedMemorySize, SMEMSZ);

    dim3 grid(SS / TQ, BB);
    attn_mma_kernel<<<grid, NTH, SMEMSZ>>>(q, k, v, out, attn);
}